// round 3
// baseline (speedup 1.0000x reference)
#include <cuda_runtime.h>
#include <math.h>

// ---------------------------------------------------------------------------
// StyleGAN2 up-2x synthesis layer, restructured:
//   Stage 0: per-cout L2-normalize + spatially flip weights -> g_wt[tap][cin][co]
//   Stage 1: parity-decomposed channel-mix conv: z = wf (*) upsample2(x)
//            z stored padded [8][256][132][136] fp32 (only [0,131) read later)
//   Stage 2: 4x4 FIR (separable [1,3,3,1]/4 per axis) + noise + bias + lrelu*sqrt2
// ---------------------------------------------------------------------------

#define CK 16   // cin chunk for stage-1 shared-memory tiling

__device__ float g_wt[9 * 512 * 256];                      // [tap(ty*3+tx)][cin][co]
__device__ float g_z[(size_t)8 * 256 * 132 * 136];         // [b][co][132][136]

// ---------------------------- Stage 0: weight prep -------------------------
__global__ void prep_weights(const float* __restrict__ w) {
    int co  = blockIdx.x;           // 256 blocks
    int tid = threadIdx.x;          // 256 threads
    const float* wc = w + (size_t)co * 4608;   // [512][3][3]

    float s = 0.f;
    for (int i = tid; i < 4608; i += 256) { float v = wc[i]; s += v * v; }
    __shared__ float red[256];
    red[tid] = s;
    __syncthreads();
    for (int off = 128; off > 0; off >>= 1) {
        if (tid < off) red[tid] += red[tid + off];
        __syncthreads();
    }
    float inv = rsqrtf(red[0] + 1e-8f);

    // wf[ty][tx] = w[co][cin][2-ty][2-tx] * inv  (flipped, normalized)
    for (int i = tid; i < 4608; i += 256) {
        int cin = i / 9, r = i % 9;
        int ty = r / 3, tx = r % 3;
        float v = wc[cin * 9 + (2 - ty) * 3 + (2 - tx)] * inv;
        g_wt[(size_t)r * (512 * 256) + cin * 256 + co] = v;
    }
}

// ---------------------------- Stage 1: parity conv -------------------------
// grid: (81 tiles (9x9 over p in [0,72)), 8 co-tiles of 32, 8 batches), 256 thr
// thread: co_l = tid&31, patch(2py x 4px) = tid>>5. 32 fp32 accumulators:
//   acc[parity(ey*2+ex)][dy][dx]
__global__ __launch_bounds__(256) void stage1(const float* __restrict__ x) {
    int tile = blockIdx.x;
    int tly = tile / 9, tlx = tile % 9;
    int p0y = tly * 8, p0x = tlx * 8;
    int co0 = blockIdx.y * 32;
    int b   = blockIdx.z;
    int tid = threadIdx.x;
    int co_l  = tid & 31;
    int patch = tid >> 5;                 // 0..7
    int py0 = (patch >> 1) * 2;           // 0,2,4,6
    int px0 = (patch & 1) * 4;            // 0,4

    // shared: phase A: xs[CK][9][12] (1728 f) + ws[9][CK][32] (4608 f)
    //         phase B: zstage[32][257] (8224 f)  -- aliased
    __shared__ __align__(16) float smbuf[8224];
    float (*xs)[9][12]  = (float (*)[9][12])smbuf;
    float (*ws)[CK][32] = (float (*)[CK][32])(smbuf + CK * 108);

    float acc[4][2][4];
#pragma unroll
    for (int p = 0; p < 4; p++)
#pragma unroll
        for (int i = 0; i < 2; i++)
#pragma unroll
            for (int j = 0; j < 4; j++) acc[p][i][j] = 0.f;

    const float* xb = x + (size_t)b * 512 * 4096;

    for (int c0 = 0; c0 < 512; c0 += CK) {
        __syncthreads();
        // load x halo tile: xs[c][j][i] = x[b][c0+c][p0y-1+j][p0x-1+i] (0 if OOR)
        for (int idx = tid; idx < CK * 81; idx += 256) {
            int c = idx / 81, r = idx % 81;
            int j = r / 9, i = r % 9;
            int gy = p0y - 1 + j, gx = p0x - 1 + i;
            float v = 0.f;
            if ((unsigned)gy < 64u && (unsigned)gx < 64u)
                v = xb[(size_t)(c0 + c) * 4096 + gy * 64 + gx];
            xs[c][j][i] = v;
        }
        // load weights: ws[tap][c][co]
        for (int idx = tid; idx < 9 * CK * 32; idx += 256) {
            int tap = idx / (CK * 32);
            int rem = idx % (CK * 32);
            int c = rem >> 5, co = rem & 31;
            ws[tap][c][co] =
                g_wt[(size_t)tap * (512 * 256) + (c0 + c) * 256 + co0 + co];
        }
        __syncthreads();

#pragma unroll
        for (int c = 0; c < CK; c++) {
            float wv[9];
#pragma unroll
            for (int k = 0; k < 9; k++) wv[k] = ws[k][c][co_l];
            float xv[3][5];
#pragma unroll
            for (int j = 0; j < 3; j++) {
                float4 v4 = *(const float4*)&xs[c][py0 + j][px0];
                xv[j][0] = v4.x; xv[j][1] = v4.y;
                xv[j][2] = v4.z; xv[j][3] = v4.w;
                xv[j][4] = xs[c][py0 + j][px0 + 4];
            }
#pragma unroll
            for (int dy = 0; dy < 2; dy++) {
#pragma unroll
                for (int dx = 0; dx < 4; dx++) {
                    float xmm = xv[dy][dx];       // x[p-1, q-1]
                    float xm0 = xv[dy][dx + 1];   // x[p-1, q  ]
                    float x0m = xv[dy + 1][dx];   // x[p  , q-1]
                    float x00 = xv[dy + 1][dx + 1];
                    acc[0][dy][dx] += wv[4] * xmm;                     // z[2p ,2q ]
                    acc[1][dy][dx] += wv[3] * xmm + wv[5] * xm0;       // z[2p ,2q+1]
                    acc[2][dy][dx] += wv[1] * xmm + wv[7] * x0m;       // z[2p+1,2q ]
                    acc[3][dy][dx] += wv[0] * xmm + wv[2] * xm0
                                    + wv[6] * x0m + wv[8] * x00;       // z[2p+1,2q+1]
                }
            }
        }
    }

    // --------- transpose through smem for coalesced global stores ----------
    __syncthreads();
    float* zstage = smbuf;                 // [co(32)][257] padded
#pragma unroll
    for (int ey = 0; ey < 2; ey++)
#pragma unroll
        for (int dy = 0; dy < 2; dy++)
#pragma unroll
            for (int ex = 0; ex < 2; ex++)
#pragma unroll
                for (int dx = 0; dx < 4; dx++) {
                    int ny = 2 * (py0 + dy) + ey;
                    int nx = 2 * (px0 + dx) + ex;
                    zstage[co_l * 257 + ny * 16 + nx] = acc[ey * 2 + ex][dy][dx];
                }
    __syncthreads();

    float* zb = g_z + (size_t)(b * 256 + co0) * (132 * 136);
#pragma unroll
    for (int s = 0; s < 32; s++) {
        int flat = s * 256 + tid;
        int cx = flat & 15;
        int r  = (flat >> 4) & 15;
        int co = flat >> 8;
        if (p0y + (r >> 1) < 66 && p0x + (cx >> 1) < 66) {
            int Ny = 2 * p0y + r, Nx = 2 * p0x + cx;
            zb[(size_t)co * (132 * 136) + Ny * 136 + Nx] =
                zstage[co * 257 + r * 16 + cx];
        }
    }
}

// ---------------------------- Stage 2: FIR + epilogue ----------------------
// grid: (16 tiles of 32x32, 256 co, 8 b), 256 threads, 4 px/thread
__global__ __launch_bounds__(256) void stage2(const float* __restrict__ bias,
                                              const float* __restrict__ noise,
                                              const float* __restrict__ nstr,
                                              float* __restrict__ out) {
    int bx  = blockIdx.x;
    int my0 = (bx >> 2) * 32, mx0 = (bx & 3) * 32;
    int co  = blockIdx.y, b = blockIdx.z;
    int tid = threadIdx.x;

    __shared__ float zs[35][36];
    const float* zp = g_z + (size_t)(b * 256 + co) * (132 * 136);
    for (int idx = tid; idx < 35 * 35; idx += 256) {
        int r = idx / 35, c = idx % 35;
        zs[r][c] = zp[(my0 + r) * 136 + mx0 + c];   // reads stay < 132 rows/cols
    }
    __syncthreads();

    float ns = *nstr;
    float bv = bias[co];
    const float c4[4] = {0.25f, 0.75f, 0.75f, 0.25f};  // [1,3,3,1]/4 per axis
    float* op = out + ((size_t)(b * 256 + co) * 128 + my0) * 128 + mx0;

#pragma unroll
    for (int k = 0; k < 4; k++) {
        int pid = k * 256 + tid;
        int py = pid >> 5, px = pid & 31;
        float s = 0.f;
#pragma unroll
        for (int ky = 0; ky < 4; ky++) {
            float t = 0.f;
#pragma unroll
            for (int kx = 0; kx < 4; kx++) t += c4[kx] * zs[py + ky][px + kx];
            s += c4[ky] * t;
        }
        s += noise[(my0 + py) * 128 + mx0 + px] * ns + bv;
        s = (s >= 0.f ? s : 0.2f * s) * 1.41421356237309515f;
        op[py * 128 + px] = s;
    }
}

// ---------------------------------------------------------------------------
extern "C" void kernel_launch(void* const* d_in, const int* in_sizes, int n_in,
                              void* d_out, int out_size) {
    (void)in_sizes; (void)n_in; (void)out_size;
    const float* x     = (const float*)d_in[0];   // [8,512,64,64]
    const float* w     = (const float*)d_in[1];   // [256,512,3,3]
    const float* bias  = (const float*)d_in[2];   // [256]
    const float* noise = (const float*)d_in[3];   // [128,128]
    const float* nstr  = (const float*)d_in[4];   // scalar
    float* out = (float*)d_out;                   // [8,256,128,128]

    prep_weights<<<256, 256>>>(w);

    dim3 g1(81, 8, 8);       // 9x9 spatial tiles (p in [0,72)), 8 co-tiles, 8 b
    stage1<<<g1, 256>>>(x);

    dim3 g2(16, 256, 8);
    stage2<<<g2, 256>>>(bias, noise, nstr, out);
}